// round 13
// baseline (speedup 1.0000x reference)
#include <cuda_runtime.h>
#include <cuda_bf16.h>
#include <cstdint>

// out = relu( [residues | atoms | meanS(atoms) | meanD(atoms)] @ [Wr; Wv; Wsr; Wdr] )
// mma.sync m16n8k16 bf16, 3-way split (hi*hi + hi*lo + lo*hi), fp32 reg accum.
// R13 = R12 with the producer coverage bug fixed: R12 issued 1024 16B-units per
// chunk but a 128x64 f32 tile needs 2048 (rows 64..127 were never produced ->
// chunk 0 read uninitialized smem -> inf). Each t-step now produces TWO units.

namespace {
constexpr int NA = 100000, AD = 12, RD = 1024, FD = 128, KN = 10;
constexpr int MT = 128;             // rows per CTA
constexpr int KC = 64;              // K chunk
constexpr int NCH = RD / KC;        // 16 residue chunks
constexpr int NCHT = NCH + 1;       // +1 ext chunk (atoms|meanS|meanD)
constexpr int CTAS = (NA + MT - 1) / MT;  // 782
constexpr long long NF = (long long)NA * FD;
constexpr long long NK = (long long)NA * KN;

// smem layout (bytes): A[2 bufs][hi 16KB | lo 16KB] then B
constexpr int SM_A   = 0;            // 2 x 32KB
constexpr int ABUF_STRIDE = 32768;
constexpr int ALO_OFF = 16384;
constexpr int SM_B   = 65536;        // 32 KB B fragments (2048 x uint4, linear)
constexpr int SM_TOTAL = 98304;      // 96 KB -> 2 CTAs/SM

constexpr int NFRAGS = NCHT * 16 * 4 * 32; // [chunk][nfrag16][t4][lane32]
}  // namespace

__device__ uint4 g_Bfrag[NFRAGS];  // B in mma-frag order: (hi0,hi1,lo0,lo1)

static __device__ __forceinline__ uint32_t sw128(uint32_t off) { return off ^ ((off >> 3) & 0x70); }
static __device__ __forceinline__ uint32_t smem_u32(const void* p) {
  uint32_t a;
  asm("{ .reg .u64 t; cvta.to.shared.u64 t, %1; cvt.u32.u64 %0, t; }" : "=r"(a) : "l"(p));
  return a;
}
static __device__ __forceinline__ void ldm4(uint32_t r[4], uint32_t addr) {
  asm volatile("ldmatrix.sync.aligned.m8n8.x4.shared.b16 {%0,%1,%2,%3}, [%4];"
               : "=r"(r[0]), "=r"(r[1]), "=r"(r[2]), "=r"(r[3]) : "r"(addr));
}
static __device__ __forceinline__ void mma16816(float c[4], const uint32_t a[4],
                                                uint32_t b0, uint32_t b1) {
  asm volatile(
      "mma.sync.aligned.m16n8k16.row.col.f32.bf16.bf16.f32 "
      "{%0,%1,%2,%3}, {%4,%5,%6,%7}, {%8,%9}, {%0,%1,%2,%3};"
      : "+f"(c[0]), "+f"(c[1]), "+f"(c[2]), "+f"(c[3])
      : "r"(a[0]), "r"(a[1]), "r"(a[2]), "r"(a[3]), "r"(b0), "r"(b1));
}
static __device__ __forceinline__ uint16_t bfbits(__nv_bfloat16 h) {
  return *reinterpret_cast<uint16_t*>(&h);
}
static __device__ __forceinline__ void cpasync16(uint32_t dst, const void* src, int srcsz) {
  asm volatile("cp.async.cg.shared.global [%0], [%1], 16, %2;"
               :: "r"(dst), "l"(src), "r"(srcsz) : "memory");
}
// pair = {lo: a, hi: b} as bf16x2
static __device__ __forceinline__ uint32_t bf16x2_rn(float a, float b) {
  uint32_t r;
  asm("cvt.rn.bf16x2.f32 %0, %1, %2;" : "=r"(r) : "f"(b), "f"(a));
  return r;
}
#define CP_COMMIT()  asm volatile("cp.async.commit_group;" ::: "memory")
#define CP_WAIT(n)   asm volatile("cp.async.wait_group %0;" :: "n"(n) : "memory")

// ---- prep: B-fragment bake + index passthrough, merged into ONE launch ----
__global__ void prep_kernel(const float* __restrict__ Wr, const float* __restrict__ Wv,
                            const float* __restrict__ Wsr, const float* __restrict__ Wdr,
                            const int* __restrict__ s0, const int* __restrict__ d0,
                            const int* __restrict__ s1, const int* __restrict__ d1,
                            float* __restrict__ out) {
  long long i = (long long)blockIdx.x * blockDim.x + threadIdx.x;
  if (i < NFRAGS) {
    int ii = (int)i;
    int lane = ii & 31, t = (ii >> 5) & 3, fn = (ii >> 7) & 15, c = ii >> 11;
    int n = fn * 8 + (lane >> 2);
    int k0 = t * 16 + 2 * (lane & 3);
    uint16_t h[4], l[4];
#pragma unroll
    for (int e = 0; e < 4; e++) {
      int kk = k0 + (e & 1) + (e >> 1) * 8;  // {k0,k0+1,k0+8,k0+9}
      float val = 0.f;
      if (c < NCH)          val = Wr[(c * KC + kk) * FD + n];
      else if (kk < AD)     val = Wv[kk * FD + n];
      else if (kk < 2 * AD) val = Wsr[(kk - AD) * FD + n];
      else if (kk < 3 * AD) val = Wdr[(kk - 2 * AD) * FD + n];
      __nv_bfloat16 hb = __float2bfloat16_rn(val);
      __nv_bfloat16 lb = __float2bfloat16_rn(val - __bfloat162float(hb));
      h[e] = bfbits(hb); l[e] = bfbits(lb);
    }
    uint4 o;
    o.x = (uint32_t)h[0] | ((uint32_t)h[1] << 16);
    o.y = (uint32_t)h[2] | ((uint32_t)h[3] << 16);
    o.z = (uint32_t)l[0] | ((uint32_t)l[1] << 16);
    o.w = (uint32_t)l[2] | ((uint32_t)l[3] << 16);
    g_Bfrag[ii] = o;
  }
  if (i < 4 * NK) {
    int reg = (int)(i / NK);
    long long j = i % NK;
    const int* src = reg == 0 ? s0 : reg == 1 ? d0 : reg == 2 ? s1 : d1;
    long long base = reg == 0 ? NF : reg == 1 ? NF + NK
                   : reg == 2 ? 2 * NF + 2 * NK : 2 * NF + 3 * NK;
    out[base + j] = (float)src[j];
  }
}

// ---- main fused kernel ----
__global__ void __launch_bounds__(256, 2)
gnn_mma_kernel(const float* __restrict__ atoms0, const float* __restrict__ resd0,
               const int* __restrict__ same0, const int* __restrict__ diff0,
               const float* __restrict__ atoms1, const float* __restrict__ resd1,
               const int* __restrict__ same1, const int* __restrict__ diff1,
               float* __restrict__ out) {
  extern __shared__ char smem[];
  const int tid = threadIdx.x, wid = tid >> 5, lane = tid & 31;
  const int p = blockIdx.x / CTAS, tile = blockIdx.x % CTAS;
  const float* atoms = p ? atoms1 : atoms0;
  const float* resd  = p ? resd1  : resd0;
  const int*   same  = p ? same1  : same0;
  const int*   diff  = p ? diff1  : diff0;
  float* outp = out + (p ? (NF + 2 * NK) : 0);
  const int r0 = tile * MT;
  const uint32_t sbase = smem_u32(smem);
  const uint32_t bB = sbase + SM_B;

  // B fragments chunk cb -> smem (straight 32 KB copy, L2-hot)
  auto bstage = [&](int cb) {
    const uint4* src = g_Bfrag + cb * 2048;
#pragma unroll
    for (int j = 0; j < 8; j++) {
      int u = tid + 256 * j;
      cpasync16(bB + (uint32_t)u * 16, src + u, 16);
    }
    CP_COMMIT();
  };

  // prologue: B(ext) in flight while we zero + prepass
  bstage(NCH);

  // zero A buffer 0 (ext chunk pad cols + tail rows); buffer 1 is fully
  // written by the interleaved producer (incl. zeros for tail rows).
  {
    uint4 z = make_uint4(0, 0, 0, 0);
    uint4* e = (uint4*)(smem + SM_A);
#pragma unroll
    for (int j = 0; j < 8; j++) e[tid + 256 * j] = z;  // 32 KB
  }
  __syncthreads();

  // ---- prepass: ext rows = [atoms | meanSame | meanDiff | 0] into A[0] ----
  for (int rr = 0; rr < 16; rr++) {
    int i = wid * 16 + rr;
    long long g = r0 + i;
    float av = 0.f;
    int idxreg = -1;
    if (g < NA) {
      if (lane < AD) av = atoms[g * AD + lane];
      if (lane < KN)          idxreg = same[g * KN + lane];
      else if (lane < 2 * KN) idxreg = diff[g * KN + (lane - KN)];
    }
    float ssum = 0.f, dsum = 0.f;
    int scnt = 0, dcnt = 0;
#pragma unroll
    for (int k = 0; k < KN; k++) {
      int si = __shfl_sync(0xffffffffu, idxreg, k);
      int di = __shfl_sync(0xffffffffu, idxreg, KN + k);
      if (si > -1) { scnt++; if (lane < AD) ssum += atoms[(long long)si * AD + lane]; }
      if (di > -1) { dcnt++; if (lane < AD) dsum += atoms[(long long)di * AD + lane]; }
    }
    if (lane < AD && g < NA) {
      float vals[3] = {av, ssum * (1.f / (float)(scnt > 1 ? scnt : 1)),
                           dsum * (1.f / (float)(dcnt > 1 ? dcnt : 1))};
#pragma unroll
      for (int q = 0; q < 3; q++) {
        __nv_bfloat16 hb = __float2bfloat16_rn(vals[q]);
        __nv_bfloat16 lb = __float2bfloat16_rn(vals[q] - __bfloat162float(hb));
        uint32_t off = sw128((uint32_t)i * 128 + (uint32_t)(q * AD + lane) * 2);
        *(__nv_bfloat16*)(smem + SM_A + off) = hb;
        *(__nv_bfloat16*)(smem + SM_A + ALO_OFF + off) = lb;
      }
    }
  }

  // warp tile: 2x4 grid, each warp 64(M) x 32(N)
  const int wm = (wid >> 2) * 64;
  const int fnBase = (wid & 3) * 4;
  float acc[4][4][4];
#pragma unroll
  for (int a = 0; a < 4; a++)
#pragma unroll
    for (int b = 0; b < 4; b++)
#pragma unroll
      for (int e = 0; e < 4; e++) acc[a][b][e] = 0.f;

  // compute one chunk from A[rbuf]; concurrently produce chunk cNext's bf16
  // hi/lo tiles into A[rbuf^1]. Per t-step: TWO 16B f32 units loaded at the
  // top (LDG latency hidden by the t-step's 48 MMAs), converted + stored after.
  // 4 t-steps x 2 units x 256 threads = 2048 units = full 128x64 f32 tile.
  auto computeChunk = [&](int rbuf, bool doNext, int cNext) {
    const uint32_t hiR = sbase + SM_A + (uint32_t)rbuf * ABUF_STRIDE;
    const uint32_t loR = hiR + ALO_OFF;
    const uint32_t hiW = sbase + SM_A + (uint32_t)(rbuf ^ 1) * ABUF_STRIDE;
    const uint32_t loW = hiW + ALO_OFF;
#pragma unroll
    for (int t = 0; t < 4; t++) {
      // producer loads: units pu0, pu1 (r = u>>4 in 0..127, kq = u&15)
      int pu0 = tid + 512 * t, pu1 = pu0 + 256;
      int pr0 = pu0 >> 4, pkq0 = pu0 & 15;
      int pr1 = pu1 >> 4, pkq1 = pu1 & 15;
      float4 pf0 = make_float4(0.f, 0.f, 0.f, 0.f);
      float4 pf1 = make_float4(0.f, 0.f, 0.f, 0.f);
      if (doNext) {
        long long g0 = r0 + pr0, g1 = r0 + pr1;
        if (g0 < NA) pf0 = *(const float4*)(resd + g0 * RD + (long long)cNext * KC + pkq0 * 4);
        if (g1 < NA) pf1 = *(const float4*)(resd + g1 * RD + (long long)cNext * KC + pkq1 * 4);
      }

      uint4 bq[4];
#pragma unroll
      for (int nf = 0; nf < 4; nf++) {
        uint32_t ba = bB + (uint32_t)((((fnBase + nf) * 4 + t) << 5) + lane) * 16;
        asm volatile("ld.shared.v4.u32 {%0,%1,%2,%3}, [%4];"
                     : "=r"(bq[nf].x), "=r"(bq[nf].y), "=r"(bq[nf].z), "=r"(bq[nf].w)
                     : "r"(ba));
      }
      uint32_t colsw = sw128(((uint32_t)(lane & 15)) * 128 +
                             (uint32_t)(t * 2 + (lane >> 4)) * 16);
      uint32_t aoff = (uint32_t)wm * 128 + colsw;   // + mf*2048

#pragma unroll
      for (int pass = 0; pass < 3; pass++) {
        const uint32_t srcB = (pass < 2) ? hiR : loR;
        uint32_t a0[4], a1[4];
        ldm4(a0, srcB + aoff);
#pragma unroll
        for (int mf = 0; mf < 4; mf++) {
          if (mf < 3) ldm4(a1, srcB + aoff + (uint32_t)(mf + 1) * 2048);
#pragma unroll
          for (int nf = 0; nf < 4; nf++) {
            if (pass == 1) mma16816(acc[mf][nf], a0, bq[nf].z, bq[nf].w);  // hi*lo
            else           mma16816(acc[mf][nf], a0, bq[nf].x, bq[nf].y);  // hi*hi / lo*hi
          }
          if (mf < 3) {
            a0[0] = a1[0]; a0[1] = a1[1]; a0[2] = a1[2]; a0[3] = a1[3];
          }
        }
      }

      // producer converts + stores (8B hi + 8B lo per unit; sw128 keeps
      // 8B-in-16B-unit placement: mask bits 4-6 derive from bits 7-9)
      if (doNext) {
        uint32_t hpa = bf16x2_rn(pf0.x, pf0.y);
        uint32_t hpb = bf16x2_rn(pf0.z, pf0.w);
        uint32_t lpa = bf16x2_rn(pf0.x - __uint_as_float(hpa << 16),
                                 pf0.y - __uint_as_float(hpa & 0xFFFF0000u));
        uint32_t lpb = bf16x2_rn(pf0.z - __uint_as_float(hpb << 16),
                                 pf0.w - __uint_as_float(hpb & 0xFFFF0000u));
        uint32_t so0 = sw128((uint32_t)pr0 * 128 + (uint32_t)pkq0 * 8);
        asm volatile("st.shared.v2.u32 [%0], {%1, %2};" :: "r"(hiW + so0), "r"(hpa), "r"(hpb) : "memory");
        asm volatile("st.shared.v2.u32 [%0], {%1, %2};" :: "r"(loW + so0), "r"(lpa), "r"(lpb) : "memory");

        uint32_t hpc = bf16x2_rn(pf1.x, pf1.y);
        uint32_t hpd = bf16x2_rn(pf1.z, pf1.w);
        uint32_t lpc = bf16x2_rn(pf1.x - __uint_as_float(hpc << 16),
                                 pf1.y - __uint_as_float(hpc & 0xFFFF0000u));
        uint32_t lpd = bf16x2_rn(pf1.z - __uint_as_float(hpd << 16),
                                 pf1.w - __uint_as_float(hpd & 0xFFFF0000u));
        uint32_t so1 = sw128((uint32_t)pr1 * 128 + (uint32_t)pkq1 * 8);
        asm volatile("st.shared.v2.u32 [%0], {%1, %2};" :: "r"(hiW + so1), "r"(hpc), "r"(hpd) : "memory");
        asm volatile("st.shared.v2.u32 [%0], {%1, %2};" :: "r"(loW + so1), "r"(lpc), "r"(lpd) : "memory");
      }
    }
  };

  // ---- ext chunk: B(ext) already in flight; produce chunk 0 into A[1] ----
  CP_WAIT(0);       // own B(ext) copies done
  __syncthreads();  // ALL threads' B(ext) + prepass writes visible
  computeChunk(0, true, 0);

  // ---- residue chunks ----
  for (int c = 0; c < NCH; c++) {
    __syncthreads();            // A(c) tiles complete; B buffer free
    bstage(c);                  // B(c) copy (L2-hot, short)
    CP_WAIT(0);
    __syncthreads();            // ALL threads' B(c) copies visible
    computeChunk((c + 1) & 1, c + 1 < NCH, c + 1);
  }

  // ---- epilogue: relu + float2 stores straight from fragments ----
  const int wn = (wid & 3) * 32;
#pragma unroll
  for (int mf = 0; mf < 4; mf++) {
    long long r = (long long)r0 + wm + mf * 16 + (lane >> 2);
#pragma unroll
    for (int nf = 0; nf < 4; nf++) {
      int cb = wn + nf * 8 + 2 * (lane & 3);
      if (r < NA) {
        float2 w;
        w.x = fmaxf(acc[mf][nf][0], 0.f);
        w.y = fmaxf(acc[mf][nf][1], 0.f);
        *(float2*)(outp + r * FD + cb) = w;
      }
      if (r + 8 < NA) {
        float2 w;
        w.x = fmaxf(acc[mf][nf][2], 0.f);
        w.y = fmaxf(acc[mf][nf][3], 0.f);
        *(float2*)(outp + (r + 8) * FD + cb) = w;
      }
    }
  }
}

extern "C" void kernel_launch(void* const* d_in, const int* in_sizes, int n_in,
                              void* d_out, int out_size) {
  const float* atoms0 = (const float*)d_in[0];
  const float* resd0  = (const float*)d_in[1];
  const int*   same0  = (const int*)d_in[2];
  const int*   diff0  = (const int*)d_in[3];
  const float* atoms1 = (const float*)d_in[4];
  const float* resd1  = (const float*)d_in[5];
  const int*   same1  = (const int*)d_in[6];
  const int*   diff1  = (const int*)d_in[7];
  const float* Wv  = (const float*)d_in[8];
  const float* Wr  = (const float*)d_in[9];
  const float* Wsr = (const float*)d_in[10];
  const float* Wdr = (const float*)d_in[11];
  float* out = (float*)d_out;

  cudaFuncSetAttribute(gnn_mma_kernel, cudaFuncAttributeMaxDynamicSharedMemorySize, SM_TOTAL);

  long long pn = 4 * NK;  // covers NFRAGS too
  prep_kernel<<<(int)((pn + 255) / 256), 256>>>(Wr, Wv, Wsr, Wdr,
                                                same0, diff0, same1, diff1, out);
  gnn_mma_kernel<<<2 * CTAS, 256, SM_TOTAL>>>(atoms0, resd0, same0, diff0,
                                              atoms1, resd1, same1, diff1, out);
}

// round 14
// speedup vs baseline: 1.7633x; 1.7633x over previous
#include <cuda_runtime.h>
#include <cuda_bf16.h>
#include <cstdint>

// out = relu( [residues | ext] @ [Wr; Wv|Wsr|Wdr] ),  ext = [atoms|meanS|meanD|0]
// mma.sync m16n8k16 bf16 3-way split (hi*hi + hi*lo + lo*hi), fp32 reg accum.
// R14: decoupled pipeline. KC=32; f32 stage = 3-slot cp.async ring filled TWO
// chunks ahead (waits never block); producer (f32->bf16 hi/lo) folded into the
// compute loop but reading from SMEM stage (fixes R13's in-warp LDG stall);
// gather prepass + ext rows moved into prep kernel via g_ext scratch so the
// main kernel is a uniform 34-chunk GEMM with 2 barriers/chunk.

namespace {
constexpr int NA = 100000, AD = 12, RD = 1024, FD = 128, KN = 10;
constexpr int MT = 128;
constexpr int KC = 32;                  // K chunk (A row = 64B bf16, SW64)
constexpr int NRCH = RD / KC;           // 32 residue chunks
constexpr int NCHT = NRCH + 2;          // +2 ext chunks (rank 36 -> 64 cols)
constexpr int EXTW = 64;
constexpr int CTAS = (NA + MT - 1) / MT;  // 782
constexpr long long NF = (long long)NA * FD;
constexpr long long NK = (long long)NA * KN;

// smem (bytes)
constexpr int STG_SLOT = 16384;         // f32 chunk: 128 rows x 128B (sw128)
constexpr int SM_STG = 0;               // 3 slots = 48KB
constexpr int SM_A = 49152;             // 2 slots x 16KB (hi 8KB @+0, lo @+8192)
constexpr int A_SLOT = 16384;
constexpr int A_LO = 8192;
constexpr int SM_B = 81920;             // 2 slots x 16KB
constexpr int B_SLOT = 16384;
constexpr int SM_TOTAL = 114688;        // 112KB -> 2 CTAs/SM (224 <= 228)

constexpr int NFRAGS = NCHT * 16 * 2 * 32;  // [chunk][nf16][t2][lane32] = 34816
constexpr int BAKE_BLKS = (NFRAGS + 255) / 256;          // 136
constexpr int IDX_BLKS  = (int)((4 * NK + 255) / 256);   // 15625
constexpr int GATH_BLKS = (2 * NA + 7) / 8;              // 25000
}  // namespace

__device__ uint4 g_Bfrag[NFRAGS];             // B frags (hi0,hi1,lo0,lo1)
__device__ float g_ext[2LL * NA * EXTW];      // ext rows, 51.2MB scratch

static __device__ __forceinline__ uint32_t sw128(uint32_t o) { return o ^ ((o >> 3) & 0x70); }
static __device__ __forceinline__ uint32_t sw64(uint32_t o)  { return o ^ ((o >> 3) & 0x30); }
static __device__ __forceinline__ uint32_t smem_u32(const void* p) {
  uint32_t a;
  asm("{ .reg .u64 t; cvta.to.shared.u64 t, %1; cvt.u32.u64 %0, t; }" : "=r"(a) : "l"(p));
  return a;
}
static __device__ __forceinline__ void ldm4(uint32_t r[4], uint32_t addr) {
  asm volatile("ldmatrix.sync.aligned.m8n8.x4.shared.b16 {%0,%1,%2,%3}, [%4];"
               : "=r"(r[0]), "=r"(r[1]), "=r"(r[2]), "=r"(r[3]) : "r"(addr));
}
static __device__ __forceinline__ void mma16816(float c[4], const uint32_t a[4],
                                                uint32_t b0, uint32_t b1) {
  asm volatile(
      "mma.sync.aligned.m16n8k16.row.col.f32.bf16.bf16.f32 "
      "{%0,%1,%2,%3}, {%4,%5,%6,%7}, {%8,%9}, {%0,%1,%2,%3};"
      : "+f"(c[0]), "+f"(c[1]), "+f"(c[2]), "+f"(c[3])
      : "r"(a[0]), "r"(a[1]), "r"(a[2]), "r"(a[3]), "r"(b0), "r"(b1));
}
static __device__ __forceinline__ uint16_t bfbits(__nv_bfloat16 h) {
  return *reinterpret_cast<uint16_t*>(&h);
}
static __device__ __forceinline__ void cpasync16(uint32_t dst, const void* src, int srcsz) {
  asm volatile("cp.async.cg.shared.global [%0], [%1], 16, %2;"
               :: "r"(dst), "l"(src), "r"(srcsz) : "memory");
}
static __device__ __forceinline__ uint32_t bf16x2_rn(float a, float b) {
  uint32_t r;
  asm("cvt.rn.bf16x2.f32 %0, %1, %2;" : "=r"(r) : "f"(b), "f"(a));
  return r;
}
static __device__ __forceinline__ void lds128f(float4& f, uint32_t a) {
  asm volatile("ld.shared.v4.f32 {%0,%1,%2,%3}, [%4];"
               : "=f"(f.x), "=f"(f.y), "=f"(f.z), "=f"(f.w) : "r"(a));
}
#define CP_COMMIT()  asm volatile("cp.async.commit_group;" ::: "memory")
#define CP_WAIT(n)   asm volatile("cp.async.wait_group %0;" :: "n"(n) : "memory")

// ---- prep: B bake + index passthrough + gather/ext, ONE launch ----
__global__ void prep_kernel(const float* __restrict__ Wr, const float* __restrict__ Wv,
                            const float* __restrict__ Wsr, const float* __restrict__ Wdr,
                            const float* __restrict__ atoms0, const float* __restrict__ atoms1,
                            const int* __restrict__ s0, const int* __restrict__ d0,
                            const int* __restrict__ s1, const int* __restrict__ d1,
                            float* __restrict__ out) {
  int b = blockIdx.x, tid = threadIdx.x;
  if (b < BAKE_BLKS) {
    int ii = b * 256 + tid;
    if (ii < NFRAGS) {
      int lane = ii & 31, t = (ii >> 5) & 1, fn = (ii >> 6) & 15, c = ii >> 10;
      int n = fn * 8 + (lane >> 2);
      int k0 = t * 16 + 2 * (lane & 3);
      uint16_t h[4], l[4];
#pragma unroll
      for (int e = 0; e < 4; e++) {
        int kl = k0 + (e & 1) + (e >> 1) * 8;   // local k in [0,32)
        float val = 0.f;
        if (c < NRCH) {
          val = Wr[(c * KC + kl) * FD + n];
        } else {
          int ke = (c - NRCH) * KC + kl;        // [0,64)
          if (ke < AD)          val = Wv[ke * FD + n];
          else if (ke < 2 * AD) val = Wsr[(ke - AD) * FD + n];
          else if (ke < 3 * AD) val = Wdr[(ke - 2 * AD) * FD + n];
        }
        __nv_bfloat16 hb = __float2bfloat16_rn(val);
        __nv_bfloat16 lb = __float2bfloat16_rn(val - __bfloat162float(hb));
        h[e] = bfbits(hb); l[e] = bfbits(lb);
      }
      uint4 o;
      o.x = (uint32_t)h[0] | ((uint32_t)h[1] << 16);
      o.y = (uint32_t)h[2] | ((uint32_t)h[3] << 16);
      o.z = (uint32_t)l[0] | ((uint32_t)l[1] << 16);
      o.w = (uint32_t)l[2] | ((uint32_t)l[3] << 16);
      g_Bfrag[ii] = o;
    }
  } else if (b < BAKE_BLKS + IDX_BLKS) {
    long long i = (long long)(b - BAKE_BLKS) * 256 + tid;
    if (i < 4 * NK) {
      int reg = (int)(i / NK);
      long long j = i % NK;
      const int* src = reg == 0 ? s0 : reg == 1 ? d0 : reg == 2 ? s1 : d1;
      long long base = reg == 0 ? NF : reg == 1 ? NF + NK
                     : reg == 2 ? 2 * NF + 2 * NK : 2 * NF + 3 * NK;
      out[base + j] = (float)src[j];
    }
  } else {
    int row = (b - BAKE_BLKS - IDX_BLKS) * 8 + (tid >> 5);
    int lane = tid & 31;
    if (row < 2 * NA) {
      int p = row >= NA ? 1 : 0;
      long long g = row - (long long)p * NA;
      const float* atoms = p ? atoms1 : atoms0;
      const int* same = p ? s1 : s0;
      const int* diff = p ? d1 : d0;
      float av = 0.f;
      int idxreg = -1;
      if (lane < AD) av = atoms[g * AD + lane];
      if (lane < KN)          idxreg = same[g * KN + lane];
      else if (lane < 2 * KN) idxreg = diff[g * KN + (lane - KN)];
      float ssum = 0.f, dsum = 0.f;
      int scnt = 0, dcnt = 0;
#pragma unroll
      for (int k = 0; k < KN; k++) {
        int si = __shfl_sync(0xffffffffu, idxreg, k);
        int di = __shfl_sync(0xffffffffu, idxreg, KN + k);
        if (si > -1) { scnt++; if (lane < AD) ssum += atoms[(long long)si * AD + lane]; }
        if (di > -1) { dcnt++; if (lane < AD) dsum += atoms[(long long)di * AD + lane]; }
      }
      float* dst = g_ext + ((long long)p * NA + g) * EXTW;
      if (lane < AD) {
        dst[lane]          = av;
        dst[AD + lane]     = ssum * (1.f / (float)(scnt > 1 ? scnt : 1));
        dst[2 * AD + lane] = dsum * (1.f / (float)(dcnt > 1 ? dcnt : 1));
      }
      if (lane >= 4) dst[32 + lane] = 0.f;   // pad cols 36..63
    }
  }
}

// ---- main fused kernel: uniform 34-chunk pipelined GEMM ----
__global__ void __launch_bounds__(256, 2)
gnn_mma_kernel(const float* __restrict__ resd0, const float* __restrict__ resd1,
               float* __restrict__ out) {
  extern __shared__ char smem[];
  const int tid = threadIdx.x, wid = tid >> 5, lane = tid & 31;
  const int p = blockIdx.x / CTAS, tile = blockIdx.x % CTAS;
  const float* resd = p ? resd1 : resd0;
  const float* gext = g_ext + (long long)p * NA * EXTW;
  float* outp = out + (p ? (NF + 2 * NK) : 0);
  const int r0 = tile * MT;
  const uint32_t sbase = smem_u32(smem);

  // f32 chunk c -> stage ring slot (cp.async, fire-and-forget)
  auto stageChunk = [&](int c, int slot) {
    uint32_t sb = sbase + SM_STG + (uint32_t)slot * STG_SLOT;
#pragma unroll
    for (int j = 0; j < 4; j++) {
      int u = tid + 256 * j;            // 1024 16B-units: r=u>>3, kq=u&7
      int r = u >> 3, kq = u & 7;
      long long g = r0 + r;
      const float* src;
      if (c < NRCH) src = resd + (g < NA ? g * RD + (long long)c * KC + kq * 4 : 0);
      else          src = gext + (g < NA ? g * EXTW + (long long)(c - NRCH) * KC + kq * 4 : 0);
      cpasync16(sb + sw128((uint32_t)r * 128 + (uint32_t)kq * 16), src, g < NA ? 16 : 0);
    }
    CP_COMMIT();
  };
  // B chunk -> slot (L2-hot 16KB copy)
  auto bstage = [&](int c, int slot) {
    const uint4* src = g_Bfrag + c * 1024;
    uint32_t dst = sbase + SM_B + (uint32_t)slot * B_SLOT;
#pragma unroll
    for (int j = 0; j < 4; j++) {
      int u = tid + 256 * j;
      cpasync16(dst + (uint32_t)u * 16, src + u, 16);
    }
    CP_COMMIT();
  };

  // prologue: stage(0), stage(1), B(0) in flight
  stageChunk(0, 0);
  stageChunk(1, 1);
  bstage(0, 0);
  CP_WAIT(2);        // stage(0) done
  __syncthreads();
  // pre-loop convert: stage slot0 -> A slot0
  {
    uint32_t sb = sbase + SM_STG;
    uint32_t aH = sbase + SM_A, aL = aH + A_LO;
#pragma unroll
    for (int j = 0; j < 4; j++) {
      int u = tid + 256 * j;
      int r = u >> 3, kq = u & 7;
      float4 f;
      lds128f(f, sb + sw128((uint32_t)r * 128 + (uint32_t)kq * 16));
      uint32_t h0 = bf16x2_rn(f.x, f.y), h1 = bf16x2_rn(f.z, f.w);
      uint32_t l0 = bf16x2_rn(f.x - __uint_as_float(h0 << 16),
                              f.y - __uint_as_float(h0 & 0xFFFF0000u));
      uint32_t l1 = bf16x2_rn(f.z - __uint_as_float(h1 << 16),
                              f.w - __uint_as_float(h1 & 0xFFFF0000u));
      uint32_t ao = sw64((uint32_t)r * 64 + (uint32_t)kq * 8);
      asm volatile("st.shared.v2.u32 [%0], {%1, %2};" :: "r"(aH + ao), "r"(h0), "r"(h1) : "memory");
      asm volatile("st.shared.v2.u32 [%0], {%1, %2};" :: "r"(aL + ao), "r"(l0), "r"(l1) : "memory");
    }
  }

  // warp tile 64(M) x 32(N)
  const int wm = (wid >> 2) * 64;
  const int fnBase = (wid & 3) * 4;
  float acc[4][4][4];
#pragma unroll
  for (int a = 0; a < 4; a++)
#pragma unroll
    for (int b2 = 0; b2 < 4; b2++)
#pragma unroll
      for (int e = 0; e < 4; e++) acc[a][b2][e] = 0.f;

  for (int c = 0; c < NCHT; c++) {
    __syncthreads();                       // compute(c-1) done: slots recyclable
    if (c + 2 < NCHT) stageChunk(c + 2, (c + 2) % 3); else CP_COMMIT();
    if (c + 1 < NCHT) bstage(c + 1, (c + 1) & 1);     else CP_COMMIT();
    CP_WAIT(2);                            // stage(c+1) + B(c) complete
    __syncthreads();                       // cross-thread visibility + A(c) ready

    const int rbuf = c & 1;
    const bool doNext = (c + 1 < NCHT);
    const uint32_t hiR = sbase + SM_A + (uint32_t)rbuf * A_SLOT;
    const uint32_t loR = hiR + A_LO;
    const uint32_t hiW = sbase + SM_A + (uint32_t)(rbuf ^ 1) * A_SLOT;
    const uint32_t loW = hiW + A_LO;
    const uint32_t bS  = sbase + SM_B + (uint32_t)(c & 1) * B_SLOT;
    const uint32_t stW = sbase + SM_STG + (uint32_t)((c + 1) % 3) * STG_SLOT;

#pragma unroll
    for (int t = 0; t < 2; t++) {
      // producer: 2 f32 units from stage ring (LDS, latency hidden by MMAs)
      int u0 = tid + 512 * t, u1 = u0 + 256;
      float4 pf0, pf1;
      if (doNext) {
        lds128f(pf0, stW + sw128((uint32_t)(u0 >> 3) * 128 + (uint32_t)(u0 & 7) * 16));
        lds128f(pf1, stW + sw128((uint32_t)(u1 >> 3) * 128 + (uint32_t)(u1 & 7) * 16));
      }
      // B fragments for this t
      uint4 bq[4];
#pragma unroll
      for (int nf = 0; nf < 4; nf++) {
        uint32_t ba = bS + (uint32_t)((((fnBase + nf) * 2 + t) << 5) + lane) * 16;
        asm volatile("ld.shared.v4.u32 {%0,%1,%2,%3}, [%4];"
                     : "=r"(bq[nf].x), "=r"(bq[nf].y), "=r"(bq[nf].z), "=r"(bq[nf].w)
                     : "r"(ba));
      }
      // A fragment offsets (SW64; full offset swizzled per mf)
      uint32_t aofs[4];
#pragma unroll
      for (int mf = 0; mf < 4; mf++)
        aofs[mf] = sw64((uint32_t)(wm + mf * 16 + (lane & 15)) * 64 +
                        (uint32_t)t * 32 + (uint32_t)(lane >> 4) * 16);

#pragma unroll
      for (int pass = 0; pass < 3; pass++) {
        const uint32_t srcB = (pass < 2) ? hiR : loR;
        uint32_t a0[4], a1[4];
        ldm4(a0, srcB + aofs[0]);
#pragma unroll
        for (int mf = 0; mf < 4; mf++) {
          if (mf < 3) ldm4(a1, srcB + aofs[mf + 1]);
#pragma unroll
          for (int nf = 0; nf < 4; nf++) {
            if (pass == 1) mma16816(acc[mf][nf], a0, bq[nf].z, bq[nf].w);  // hi*lo
            else           mma16816(acc[mf][nf], a0, bq[nf].x, bq[nf].y);  // hi*hi / lo*hi
          }
          if (mf < 3) { a0[0] = a1[0]; a0[1] = a1[1]; a0[2] = a1[2]; a0[3] = a1[3]; }
        }
      }

      // producer: convert + store into next A buffer
      if (doNext) {
        uint32_t h0 = bf16x2_rn(pf0.x, pf0.y), h1 = bf16x2_rn(pf0.z, pf0.w);
        uint32_t l0 = bf16x2_rn(pf0.x - __uint_as_float(h0 << 16),
                                pf0.y - __uint_as_float(h0 & 0xFFFF0000u));
        uint32_t l1 = bf16x2_rn(pf0.z - __uint_as_float(h1 << 16),
                                pf0.w - __uint_as_float(h1 & 0xFFFF0000u));
        uint32_t ao0 = sw64((uint32_t)(u0 >> 3) * 64 + (uint32_t)(u0 & 7) * 8);
        asm volatile("st.shared.v2.u32 [%0], {%1, %2};" :: "r"(hiW + ao0), "r"(h0), "r"(h1) : "memory");
        asm volatile("st.shared.v2.u32 [%0], {%1, %2};" :: "r"(loW + ao0), "r"(l0), "r"(l1) : "memory");
        uint32_t h2 = bf16x2_rn(pf1.x, pf1.y), h3 = bf16x2_rn(pf1.z, pf1.w);
        uint32_t l2 = bf16x2_rn(pf1.x - __uint_as_float(h2 << 16),
                                pf1.y - __uint_as_float(h2 & 0xFFFF0000u));
        uint32_t l3 = bf16x2_rn(pf1.z - __uint_as_float(h3 << 16),
                                pf1.w - __uint_as_float(h3 & 0xFFFF0000u));
        uint32_t ao1 = sw64((uint32_t)(u1 >> 3) * 64 + (uint32_t)(u1 & 7) * 8);
        asm volatile("st.shared.v2.u32 [%0], {%1, %2};" :: "r"(hiW + ao1), "r"(h2), "r"(h3) : "memory");
        asm volatile("st.shared.v2.u32 [%0], {%1, %2};" :: "r"(loW + ao1), "r"(l2), "r"(l3) : "memory");
      }
    }
  }

  // ---- epilogue: relu + float2 stores straight from fragments ----
  const int wn = (wid & 3) * 32;
#pragma unroll
  for (int mf = 0; mf < 4; mf++) {
    long long r = (long long)r0 + wm + mf * 16 + (lane >> 2);
#pragma unroll
    for (int nf = 0; nf < 4; nf++) {
      int cb = wn + nf * 8 + 2 * (lane & 3);
      if (r < NA) {
        float2 w;
        w.x = fmaxf(acc[mf][nf][0], 0.f);
        w.y = fmaxf(acc[mf][nf][1], 0.f);
        *(float2*)(outp + r * FD + cb) = w;
      }
      if (r + 8 < NA) {
        float2 w;
        w.x = fmaxf(acc[mf][nf][2], 0.f);
        w.y = fmaxf(acc[mf][nf][3], 0.f);
        *(float2*)(outp + (r + 8) * FD + cb) = w;
      }
    }
  }
}

extern "C" void kernel_launch(void* const* d_in, const int* in_sizes, int n_in,
                              void* d_out, int out_size) {
  const float* atoms0 = (const float*)d_in[0];
  const float* resd0  = (const float*)d_in[1];
  const int*   same0  = (const int*)d_in[2];
  const int*   diff0  = (const int*)d_in[3];
  const float* atoms1 = (const float*)d_in[4];
  const float* resd1  = (const float*)d_in[5];
  const int*   same1  = (const int*)d_in[6];
  const int*   diff1  = (const int*)d_in[7];
  const float* Wv  = (const float*)d_in[8];
  const float* Wr  = (const float*)d_in[9];
  const float* Wsr = (const float*)d_in[10];
  const float* Wdr = (const float*)d_in[11];
  float* out = (float*)d_out;

  cudaFuncSetAttribute(gnn_mma_kernel, cudaFuncAttributeMaxDynamicSharedMemorySize, SM_TOTAL);

  prep_kernel<<<BAKE_BLKS + IDX_BLKS + GATH_BLKS, 256>>>(
      Wr, Wv, Wsr, Wdr, atoms0, atoms1, same0, diff0, same1, diff1, out);
  gnn_mma_kernel<<<2 * CTAS, 256, SM_TOTAL>>>(resd0, resd1, out);
}

// round 16
// speedup vs baseline: 2.1837x; 1.2384x over previous
#include <cuda_runtime.h>
#include <cuda_fp16.h>
#include <cstdint>

// out = relu( [residues | ext] @ [Wr; Wv|Wsr|Wdr] ),  ext = [atoms|meanS|meanD|0]
// R16 = R15 resubmitted verbatim (R15 bench was a container-level infra failure;
// the kernel never ran). Change under test: fp16 2-term split (A = hi+lo fp16,
// B = fp16; dropped term A*deltaB -> norm-rel error ~2.8e-4 < 1e-3), MMA count
// -33% vs bf16 3-term; B ring 3-deep (8KB slots), stage ring 3-deep, ONE
// barrier per chunk. Producer (f32->fp16 hi/lo) folded into compute, reading
// from SMEM stage (R14-validated structure).

namespace {
constexpr int NA = 100000, AD = 12, RD = 1024, FD = 128, KN = 10;
constexpr int MT = 128;
constexpr int KC = 32;                  // K chunk (A row = 64B fp16, SW64)
constexpr int NRCH = RD / KC;           // 32 residue chunks
constexpr int NCHT = NRCH + 2;          // +2 ext chunks (rank 36 -> 64)
constexpr int EXTW = 64;
constexpr int CTAS = (NA + MT - 1) / MT;  // 782
constexpr long long NF = (long long)NA * FD;
constexpr long long NK = (long long)NA * KN;

// smem (bytes)
constexpr int STG_SLOT = 16384;         // f32 chunk: 128 rows x 128B (sw128)
constexpr int SM_STG = 0;               // 3 slots = 48KB
constexpr int SM_A = 49152;             // 2 slots x 16KB (hi 8KB @+0, lo @+8192)
constexpr int A_SLOT = 16384;
constexpr int A_LO = 8192;
constexpr int SM_B = 81920;             // 3 slots x 8KB
constexpr int B_SLOT = 8192;
constexpr int SM_TOTAL = 106496;        // 104KB -> 2 CTAs/SM

constexpr int NFRAGS2 = NCHT * 16 * 2 * 32;  // uint2 frags = 34816
constexpr int BAKE_BLKS = (NFRAGS2 + 255) / 256;         // 136
constexpr int IDX_BLKS  = (int)((4 * NK + 255) / 256);   // 15625
constexpr int GATH_BLKS = (2 * NA + 7) / 8;              // 25000
}  // namespace

__device__ uint2 g_Bfrag[NFRAGS2];            // B fp16 frags (b0,b1) per (c,nf,t,lane)
__device__ float g_ext[2LL * NA * EXTW];      // ext rows scratch

static __device__ __forceinline__ uint32_t sw128(uint32_t o) { return o ^ ((o >> 3) & 0x70); }
static __device__ __forceinline__ uint32_t sw64(uint32_t o)  { return o ^ ((o >> 3) & 0x30); }
static __device__ __forceinline__ uint32_t smem_u32(const void* p) {
  uint32_t a;
  asm("{ .reg .u64 t; cvta.to.shared.u64 t, %1; cvt.u32.u64 %0, t; }" : "=r"(a) : "l"(p));
  return a;
}
static __device__ __forceinline__ void ldm4(uint32_t r[4], uint32_t addr) {
  asm volatile("ldmatrix.sync.aligned.m8n8.x4.shared.b16 {%0,%1,%2,%3}, [%4];"
               : "=r"(r[0]), "=r"(r[1]), "=r"(r[2]), "=r"(r[3]) : "r"(addr));
}
static __device__ __forceinline__ void mma16816h(float c[4], const uint32_t a[4],
                                                 uint32_t b0, uint32_t b1) {
  asm volatile(
      "mma.sync.aligned.m16n8k16.row.col.f32.f16.f16.f32 "
      "{%0,%1,%2,%3}, {%4,%5,%6,%7}, {%8,%9}, {%0,%1,%2,%3};"
      : "+f"(c[0]), "+f"(c[1]), "+f"(c[2]), "+f"(c[3])
      : "r"(a[0]), "r"(a[1]), "r"(a[2]), "r"(a[3]), "r"(b0), "r"(b1));
}
static __device__ __forceinline__ void cpasync16(uint32_t dst, const void* src, int srcsz) {
  asm volatile("cp.async.cg.shared.global [%0], [%1], 16, %2;"
               :: "r"(dst), "l"(src), "r"(srcsz) : "memory");
}
// convert f32 pair -> fp16 hi pair (packed) + fp16 lo-residual pair (packed)
static __device__ __forceinline__ void h2split(float a, float b, uint32_t& hi, uint32_t& lo) {
  __half2 h = __floats2half2_rn(a, b);          // .x = a (low half)
  float2 hf = __half22float2(h);
  __half2 l = __floats2half2_rn(a - hf.x, b - hf.y);
  hi = *reinterpret_cast<uint32_t*>(&h);
  lo = *reinterpret_cast<uint32_t*>(&l);
}
static __device__ __forceinline__ void lds128f(float4& f, uint32_t a) {
  asm volatile("ld.shared.v4.f32 {%0,%1,%2,%3}, [%4];"
               : "=f"(f.x), "=f"(f.y), "=f"(f.z), "=f"(f.w) : "r"(a));
}
#define CP_COMMIT()  asm volatile("cp.async.commit_group;" ::: "memory")
#define CP_WAIT(n)   asm volatile("cp.async.wait_group %0;" :: "n"(n) : "memory")

// ---- prep: B bake (fp16) + index passthrough + gather/ext, ONE launch ----
__global__ void prep_kernel(const float* __restrict__ Wr, const float* __restrict__ Wv,
                            const float* __restrict__ Wsr, const float* __restrict__ Wdr,
                            const float* __restrict__ atoms0, const float* __restrict__ atoms1,
                            const int* __restrict__ s0, const int* __restrict__ d0,
                            const int* __restrict__ s1, const int* __restrict__ d1,
                            float* __restrict__ out) {
  int b = blockIdx.x, tid = threadIdx.x;
  if (b < BAKE_BLKS) {
    int ii = b * 256 + tid;
    if (ii < NFRAGS2) {
      int lane = ii & 31, t = (ii >> 5) & 1, fn = (ii >> 6) & 15, c = ii >> 10;
      int n = fn * 8 + (lane >> 2);
      int k0 = t * 16 + 2 * (lane & 3);
      uint16_t h[4];
#pragma unroll
      for (int e = 0; e < 4; e++) {
        int kl = k0 + (e & 1) + (e >> 1) * 8;
        float val = 0.f;
        if (c < NRCH) {
          val = Wr[(c * KC + kl) * FD + n];
        } else {
          int ke = (c - NRCH) * KC + kl;
          if (ke < AD)          val = Wv[ke * FD + n];
          else if (ke < 2 * AD) val = Wsr[(ke - AD) * FD + n];
          else if (ke < 3 * AD) val = Wdr[(ke - 2 * AD) * FD + n];
        }
        __half hb = __float2half_rn(val);
        h[e] = *reinterpret_cast<uint16_t*>(&hb);
      }
      uint2 o;
      o.x = (uint32_t)h[0] | ((uint32_t)h[1] << 16);
      o.y = (uint32_t)h[2] | ((uint32_t)h[3] << 16);
      g_Bfrag[ii] = o;
    }
  } else if (b < BAKE_BLKS + IDX_BLKS) {
    long long i = (long long)(b - BAKE_BLKS) * 256 + tid;
    if (i < 4 * NK) {
      int reg = (int)(i / NK);
      long long j = i % NK;
      const int* src = reg == 0 ? s0 : reg == 1 ? d0 : reg == 2 ? s1 : d1;
      long long base = reg == 0 ? NF : reg == 1 ? NF + NK
                     : reg == 2 ? 2 * NF + 2 * NK : 2 * NF + 3 * NK;
      out[base + j] = (float)src[j];
    }
  } else {
    int row = (b - BAKE_BLKS - IDX_BLKS) * 8 + (tid >> 5);
    int lane = tid & 31;
    if (row < 2 * NA) {
      int p = row >= NA ? 1 : 0;
      long long g = row - (long long)p * NA;
      const float* atoms = p ? atoms1 : atoms0;
      const int* same = p ? s1 : s0;
      const int* diff = p ? d1 : d0;
      float av = 0.f;
      int idxreg = -1;
      if (lane < AD) av = atoms[g * AD + lane];
      if (lane < KN)          idxreg = same[g * KN + lane];
      else if (lane < 2 * KN) idxreg = diff[g * KN + (lane - KN)];
      float ssum = 0.f, dsum = 0.f;
      int scnt = 0, dcnt = 0;
#pragma unroll
      for (int k = 0; k < KN; k++) {
        int si = __shfl_sync(0xffffffffu, idxreg, k);
        int di = __shfl_sync(0xffffffffu, idxreg, KN + k);
        if (si > -1) { scnt++; if (lane < AD) ssum += atoms[(long long)si * AD + lane]; }
        if (di > -1) { dcnt++; if (lane < AD) dsum += atoms[(long long)di * AD + lane]; }
      }
      float* dst = g_ext + ((long long)p * NA + g) * EXTW;
      if (lane < AD) {
        dst[lane]          = av;
        dst[AD + lane]     = ssum * (1.f / (float)(scnt > 1 ? scnt : 1));
        dst[2 * AD + lane] = dsum * (1.f / (float)(dcnt > 1 ? dcnt : 1));
      }
      if (lane >= 4) dst[32 + lane] = 0.f;   // pad cols 36..63
    }
  }
}

// ---- main fused kernel: uniform 34-chunk pipelined GEMM, 1 barrier/chunk ----
__global__ void __launch_bounds__(256, 2)
gnn_mma_kernel(const float* __restrict__ resd0, const float* __restrict__ resd1,
               float* __restrict__ out) {
  extern __shared__ char smem[];
  const int tid = threadIdx.x, wid = tid >> 5, lane = tid & 31;
  const int p = blockIdx.x / CTAS, tile = blockIdx.x % CTAS;
  const float* resd = p ? resd1 : resd0;
  const float* gext = g_ext + (long long)p * NA * EXTW;
  float* outp = out + (p ? (NF + 2 * NK) : 0);
  const int r0 = tile * MT;
  const uint32_t sbase = smem_u32(smem);

  auto stageChunk = [&](int c, int slot) {   // f32 chunk -> stage ring (cp.async)
    uint32_t sb = sbase + SM_STG + (uint32_t)slot * STG_SLOT;
#pragma unroll
    for (int j = 0; j < 4; j++) {
      int u = tid + 256 * j;            // 1024 16B-units: r=u>>3, kq=u&7
      int r = u >> 3, kq = u & 7;
      long long g = r0 + r;
      const float* src;
      if (c < NRCH) src = resd + (g < NA ? g * RD + (long long)c * KC + kq * 4 : 0);
      else          src = gext + (g < NA ? g * EXTW + (long long)(c - NRCH) * KC + kq * 4 : 0);
      cpasync16(sb + sw128((uint32_t)r * 128 + (uint32_t)kq * 16), src, g < NA ? 16 : 0);
    }
    CP_COMMIT();
  };
  auto bstage = [&](int c, int slot) {       // B chunk -> ring (8KB, L2-hot)
    const uint4* src = (const uint4*)(g_Bfrag + c * 1024);
    uint32_t dst = sbase + SM_B + (uint32_t)slot * B_SLOT;
#pragma unroll
    for (int j = 0; j < 2; j++) {
      int u = tid + 256 * j;
      cpasync16(dst + (uint32_t)u * 16, src + u, 16);
    }
    CP_COMMIT();
  };

  // prologue: stage(0), stage(1), B(0)
  stageChunk(0, 0);
  stageChunk(1, 1);
  bstage(0, 0);
  CP_WAIT(2);        // stage(0) done
  __syncthreads();
  // pre-loop convert: stage slot0 -> A slot0
  {
    uint32_t sb = sbase + SM_STG;
    uint32_t aH = sbase + SM_A, aL = aH + A_LO;
#pragma unroll
    for (int j = 0; j < 4; j++) {
      int u = tid + 256 * j;
      int r = u >> 3, kq = u & 7;
      float4 f;
      lds128f(f, sb + sw128((uint32_t)r * 128 + (uint32_t)kq * 16));
      uint32_t h0, l0, h1, l1;
      h2split(f.x, f.y, h0, l0);
      h2split(f.z, f.w, h1, l1);
      uint32_t ao = sw64((uint32_t)r * 64 + (uint32_t)kq * 8);
      asm volatile("st.shared.v2.u32 [%0], {%1, %2};" :: "r"(aH + ao), "r"(h0), "r"(h1) : "memory");
      asm volatile("st.shared.v2.u32 [%0], {%1, %2};" :: "r"(aL + ao), "r"(l0), "r"(l1) : "memory");
    }
  }

  // warp tile 64(M) x 32(N)
  const int wm = (wid >> 2) * 64;
  const int fnBase = (wid & 3) * 4;
  float acc[4][4][4];
#pragma unroll
  for (int a = 0; a < 4; a++)
#pragma unroll
    for (int b2 = 0; b2 < 4; b2++)
#pragma unroll
      for (int e = 0; e < 4; e++) acc[a][b2][e] = 0.f;

  for (int c = 0; c < NCHT; c++) {
    CP_WAIT(0);        // all copies from previous iteration complete (own)
    __syncthreads();   // everyone's copies visible; prev compute done (slots free)
    if (c + 2 < NCHT) stageChunk(c + 2, (c + 2) % 3);
    if (c + 1 < NCHT) bstage(c + 1, (c + 1) % 3);

    const int rbuf = c & 1;
    const bool doNext = (c + 1 < NCHT);
    const uint32_t hiR = sbase + SM_A + (uint32_t)rbuf * A_SLOT;
    const uint32_t loR = hiR + A_LO;
    const uint32_t hiW = sbase + SM_A + (uint32_t)(rbuf ^ 1) * A_SLOT;
    const uint32_t loW = hiW + A_LO;
    const uint32_t bS  = sbase + SM_B + (uint32_t)(c % 3) * B_SLOT;
    const uint32_t stW = sbase + SM_STG + (uint32_t)((c + 1) % 3) * STG_SLOT;

#pragma unroll
    for (int t = 0; t < 2; t++) {
      // producer: 2 f32 units from stage ring (LDS; latency hidden by MMAs)
      int u0 = tid + 512 * t, u1 = u0 + 256;
      float4 pf0, pf1;
      if (doNext) {
        lds128f(pf0, stW + sw128((uint32_t)(u0 >> 3) * 128 + (uint32_t)(u0 & 7) * 16));
        lds128f(pf1, stW + sw128((uint32_t)(u1 >> 3) * 128 + (uint32_t)(u1 & 7) * 16));
      }
      // B fragments (fp16, uint2 per nf)
      uint2 bq[4];
#pragma unroll
      for (int nf = 0; nf < 4; nf++) {
        uint32_t ba = bS + (uint32_t)((((fnBase + nf) * 2 + t) << 5) + lane) * 8;
        asm volatile("ld.shared.v2.u32 {%0,%1}, [%2];"
                     : "=r"(bq[nf].x), "=r"(bq[nf].y) : "r"(ba));
      }
      uint32_t aofs[4];
#pragma unroll
      for (int mf = 0; mf < 4; mf++)
        aofs[mf] = sw64((uint32_t)(wm + mf * 16 + (lane & 15)) * 64 +
                        (uint32_t)t * 32 + (uint32_t)(lane >> 4) * 16);

      // pass 0: hi;  pass 1: lo  (16 MMAs each, all-distinct accumulators)
#pragma unroll
      for (int pass = 0; pass < 2; pass++) {
        const uint32_t srcB = pass ? loR : hiR;
        uint32_t a0[4], a1[4];
        ldm4(a0, srcB + aofs[0]);
#pragma unroll
        for (int mf = 0; mf < 4; mf++) {
          if (mf < 3) ldm4(a1, srcB + aofs[mf + 1]);
#pragma unroll
          for (int nf = 0; nf < 4; nf++)
            mma16816h(acc[mf][nf], a0, bq[nf].x, bq[nf].y);
          if (mf < 3) { a0[0] = a1[0]; a0[1] = a1[1]; a0[2] = a1[2]; a0[3] = a1[3]; }
        }
      }

      // producer: convert + store into next A buffer
      if (doNext) {
        uint32_t h0, l0, h1, l1, h2, l2, h3, l3;
        h2split(pf0.x, pf0.y, h0, l0);
        h2split(pf0.z, pf0.w, h1, l1);
        uint32_t ao0 = sw64((uint32_t)(u0 >> 3) * 64 + (uint32_t)(u0 & 7) * 8);
        asm volatile("st.shared.v2.u32 [%0], {%1, %2};" :: "r"(hiW + ao0), "r"(h0), "r"(h1) : "memory");
        asm volatile("st.shared.v2.u32 [%0], {%1, %2};" :: "r"(loW + ao0), "r"(l0), "r"(l1) : "memory");
        h2split(pf1.x, pf1.y, h2, l2);
        h2split(pf1.z, pf1.w, h3, l3);
        uint32_t ao1 = sw64((uint32_t)(u1 >> 3) * 64 + (uint32_t)(u1 & 7) * 8);
        asm volatile("st.shared.v2.u32 [%0], {%1, %2};" :: "r"(hiW + ao1), "r"(h2), "r"(h3) : "memory");
        asm volatile("st.shared.v2.u32 [%0], {%1, %2};" :: "r"(loW + ao1), "r"(l2), "r"(l3) : "memory");
      }
    }
  }

  // ---- epilogue: relu + float2 stores straight from fragments ----
  const int wn = (wid & 3) * 32;
#pragma unroll
  for (int mf = 0; mf < 4; mf++) {
    long long r = (long long)r0 + wm + mf * 16 + (lane >> 2);
#pragma unroll
    for (int nf = 0; nf < 4; nf++) {
      int cb = wn + nf * 8 + 2 * (lane & 3);
      if (r < NA) {
        float2 w;
        w.x = fmaxf(acc[mf][nf][0], 0.f);
        w.y = fmaxf(acc[mf][nf][1], 0.f);
        *(float2*)(outp + r * FD + cb) = w;
      }
      if (r + 8 < NA) {
        float2 w;
        w.x = fmaxf(acc[mf][nf][2], 0.f);
        w.y = fmaxf(acc[mf][nf][3], 0.f);
        *(float2*)(outp + (r + 8) * FD + cb) = w;
      }
    }
  }
}

extern "C" void kernel_launch(void* const* d_in, const int* in_sizes, int n_in,
                              void* d_out, int out_size) {
  const float* atoms0 = (const float*)d_in[0];
  const float* resd0  = (const float*)d_in[1];
  const int*   same0  = (const int*)d_in[2];
  const int*   diff0  = (const int*)d_in[3];
  const float* atoms1 = (const float*)d_in[4];
  const float* resd1  = (const float*)d_in[5];
  const int*   same1  = (const int*)d_in[6];
  const int*   diff1  = (const int*)d_in[7];
  const float* Wv  = (const float*)d_in[8];
  const float* Wr  = (const float*)d_in[9];
  const float* Wsr = (const float*)d_in[10];
  const float* Wdr = (const float*)d_in[11];
  float* out = (float*)d_out;

  cudaFuncSetAttribute(gnn_mma_kernel, cudaFuncAttributeMaxDynamicSharedMemorySize, SM_TOTAL);

  prep_kernel<<<BAKE_BLKS + IDX_BLKS + GATH_BLKS, 256>>>(
      Wr, Wv, Wsr, Wdr, atoms0, atoms1, same0, diff0, same1, diff1, out);
  gnn_mma_kernel<<<2 * CTAS, 256, SM_TOTAL>>>(resd0, resd1, out);
}

// round 17
// speedup vs baseline: 2.6628x; 1.2194x over previous
#include <cuda_runtime.h>
#include <cuda_fp16.h>
#include <cstdint>

// out = relu( [residues | ext] @ [Wr; Wv|Wsr|Wdr] ),  ext = [atoms|meanS|meanD|0]
// R17: SINGLE-pass fp16 (A fp16, B fp16, fp32 accum). R16 calibrated the cost
// of one dropped first-order term (A*deltaB) at 2.08e-4; dropping the second
// (deltaA*B) adds an independent equal term -> ~2.9e-4 expected, 3.4x under
// the 1e-3 gate. MMA floor 189 -> 94.5us; A ldmatrix traffic halves (L1 was
// 59.5% busy, co-leading with tensor). Pipeline structure unchanged from R16:
// stage ring 3-deep (cp.async 2 ahead), B ring 3-deep, A double-buffered,
// producer folded into compute reading from SMEM stage, 1 barrier/chunk.

namespace {
constexpr int NA = 100000, AD = 12, RD = 1024, FD = 128, KN = 10;
constexpr int MT = 128;
constexpr int KC = 32;                  // K chunk (A row = 64B fp16, SW64)
constexpr int NRCH = RD / KC;           // 32 residue chunks
constexpr int NCHT = NRCH + 2;          // +2 ext chunks (rank 36 -> 64)
constexpr int EXTW = 64;
constexpr int CTAS = (NA + MT - 1) / MT;  // 782
constexpr long long NF = (long long)NA * FD;
constexpr long long NK = (long long)NA * KN;

// smem (bytes)
constexpr int STG_SLOT = 16384;         // f32 chunk: 128 rows x 128B (sw128)
constexpr int SM_STG = 0;               // 3 slots = 48KB
constexpr int SM_A = 49152;             // 2 slots x 8KB (fp16 hi only)
constexpr int A_SLOT = 8192;
constexpr int SM_B = 65536;             // 3 slots x 8KB
constexpr int B_SLOT = 8192;
constexpr int SM_TOTAL = 90112;         // 88KB -> 2 CTAs/SM

constexpr int NFRAGS2 = NCHT * 16 * 2 * 32;  // uint2 frags = 34816
constexpr int BAKE_BLKS = (NFRAGS2 + 255) / 256;         // 136
constexpr int IDX_BLKS  = (int)((4 * NK + 255) / 256);   // 15625
constexpr int GATH_BLKS = (2 * NA + 7) / 8;              // 25000
}  // namespace

__device__ uint2 g_Bfrag[NFRAGS2];            // B fp16 frags (b0,b1) per (c,nf,t,lane)
__device__ float g_ext[2LL * NA * EXTW];      // ext rows scratch

static __device__ __forceinline__ uint32_t sw128(uint32_t o) { return o ^ ((o >> 3) & 0x70); }
static __device__ __forceinline__ uint32_t sw64(uint32_t o)  { return o ^ ((o >> 3) & 0x30); }
static __device__ __forceinline__ uint32_t smem_u32(const void* p) {
  uint32_t a;
  asm("{ .reg .u64 t; cvta.to.shared.u64 t, %1; cvt.u32.u64 %0, t; }" : "=r"(a) : "l"(p));
  return a;
}
static __device__ __forceinline__ void ldm4(uint32_t r[4], uint32_t addr) {
  asm volatile("ldmatrix.sync.aligned.m8n8.x4.shared.b16 {%0,%1,%2,%3}, [%4];"
               : "=r"(r[0]), "=r"(r[1]), "=r"(r[2]), "=r"(r[3]) : "r"(addr));
}
static __device__ __forceinline__ void mma16816h(float c[4], const uint32_t a[4],
                                                 uint32_t b0, uint32_t b1) {
  asm volatile(
      "mma.sync.aligned.m16n8k16.row.col.f32.f16.f16.f32 "
      "{%0,%1,%2,%3}, {%4,%5,%6,%7}, {%8,%9}, {%0,%1,%2,%3};"
      : "+f"(c[0]), "+f"(c[1]), "+f"(c[2]), "+f"(c[3])
      : "r"(a[0]), "r"(a[1]), "r"(a[2]), "r"(a[3]), "r"(b0), "r"(b1));
}
static __device__ __forceinline__ void cpasync16(uint32_t dst, const void* src, int srcsz) {
  asm volatile("cp.async.cg.shared.global [%0], [%1], 16, %2;"
               :: "r"(dst), "l"(src), "r"(srcsz) : "memory");
}
// pack f32 pair -> fp16 pair (round-to-nearest)
static __device__ __forceinline__ uint32_t h2pack(float a, float b) {
  __half2 h = __floats2half2_rn(a, b);
  return *reinterpret_cast<uint32_t*>(&h);
}
static __device__ __forceinline__ void lds128f(float4& f, uint32_t a) {
  asm volatile("ld.shared.v4.f32 {%0,%1,%2,%3}, [%4];"
               : "=f"(f.x), "=f"(f.y), "=f"(f.z), "=f"(f.w) : "r"(a));
}
#define CP_COMMIT()  asm volatile("cp.async.commit_group;" ::: "memory")
#define CP_WAIT(n)   asm volatile("cp.async.wait_group %0;" :: "n"(n) : "memory")

// ---- prep: B bake (fp16) + index passthrough + gather/ext, ONE launch ----
__global__ void prep_kernel(const float* __restrict__ Wr, const float* __restrict__ Wv,
                            const float* __restrict__ Wsr, const float* __restrict__ Wdr,
                            const float* __restrict__ atoms0, const float* __restrict__ atoms1,
                            const int* __restrict__ s0, const int* __restrict__ d0,
                            const int* __restrict__ s1, const int* __restrict__ d1,
                            float* __restrict__ out) {
  int b = blockIdx.x, tid = threadIdx.x;
  if (b < BAKE_BLKS) {
    int ii = b * 256 + tid;
    if (ii < NFRAGS2) {
      int lane = ii & 31, t = (ii >> 5) & 1, fn = (ii >> 6) & 15, c = ii >> 10;
      int n = fn * 8 + (lane >> 2);
      int k0 = t * 16 + 2 * (lane & 3);
      uint16_t h[4];
#pragma unroll
      for (int e = 0; e < 4; e++) {
        int kl = k0 + (e & 1) + (e >> 1) * 8;
        float val = 0.f;
        if (c < NRCH) {
          val = Wr[(c * KC + kl) * FD + n];
        } else {
          int ke = (c - NRCH) * KC + kl;
          if (ke < AD)          val = Wv[ke * FD + n];
          else if (ke < 2 * AD) val = Wsr[(ke - AD) * FD + n];
          else if (ke < 3 * AD) val = Wdr[(ke - 2 * AD) * FD + n];
        }
        __half hb = __float2half_rn(val);
        h[e] = *reinterpret_cast<uint16_t*>(&hb);
      }
      uint2 o;
      o.x = (uint32_t)h[0] | ((uint32_t)h[1] << 16);
      o.y = (uint32_t)h[2] | ((uint32_t)h[3] << 16);
      g_Bfrag[ii] = o;
    }
  } else if (b < BAKE_BLKS + IDX_BLKS) {
    long long i = (long long)(b - BAKE_BLKS) * 256 + tid;
    if (i < 4 * NK) {
      int reg = (int)(i / NK);
      long long j = i % NK;
      const int* src = reg == 0 ? s0 : reg == 1 ? d0 : reg == 2 ? s1 : d1;
      long long base = reg == 0 ? NF : reg == 1 ? NF + NK
                     : reg == 2 ? 2 * NF + 2 * NK : 2 * NF + 3 * NK;
      out[base + j] = (float)src[j];
    }
  } else {
    int row = (b - BAKE_BLKS - IDX_BLKS) * 8 + (tid >> 5);
    int lane = tid & 31;
    if (row < 2 * NA) {
      int p = row >= NA ? 1 : 0;
      long long g = row - (long long)p * NA;
      const float* atoms = p ? atoms1 : atoms0;
      const int* same = p ? s1 : s0;
      const int* diff = p ? d1 : d0;
      float av = 0.f;
      int idxreg = -1;
      if (lane < AD) av = atoms[g * AD + lane];
      if (lane < KN)          idxreg = same[g * KN + lane];
      else if (lane < 2 * KN) idxreg = diff[g * KN + (lane - KN)];
      float ssum = 0.f, dsum = 0.f;
      int scnt = 0, dcnt = 0;
#pragma unroll
      for (int k = 0; k < KN; k++) {
        int si = __shfl_sync(0xffffffffu, idxreg, k);
        int di = __shfl_sync(0xffffffffu, idxreg, KN + k);
        if (si > -1) { scnt++; if (lane < AD) ssum += atoms[(long long)si * AD + lane]; }
        if (di > -1) { dcnt++; if (lane < AD) dsum += atoms[(long long)di * AD + lane]; }
      }
      float* dst = g_ext + ((long long)p * NA + g) * EXTW;
      if (lane < AD) {
        dst[lane]          = av;
        dst[AD + lane]     = ssum * (1.f / (float)(scnt > 1 ? scnt : 1));
        dst[2 * AD + lane] = dsum * (1.f / (float)(dcnt > 1 ? dcnt : 1));
      }
      if (lane >= 4) dst[32 + lane] = 0.f;   // pad cols 36..63
    }
  }
}

// ---- main fused kernel: uniform 34-chunk pipelined GEMM, 1 barrier/chunk ----
__global__ void __launch_bounds__(256, 2)
gnn_mma_kernel(const float* __restrict__ resd0, const float* __restrict__ resd1,
               float* __restrict__ out) {
  extern __shared__ char smem[];
  const int tid = threadIdx.x, wid = tid >> 5, lane = tid & 31;
  const int p = blockIdx.x / CTAS, tile = blockIdx.x % CTAS;
  const float* resd = p ? resd1 : resd0;
  const float* gext = g_ext + (long long)p * NA * EXTW;
  float* outp = out + (p ? (NF + 2 * NK) : 0);
  const int r0 = tile * MT;
  const uint32_t sbase = smem_u32(smem);

  auto stageChunk = [&](int c, int slot) {   // f32 chunk -> stage ring (cp.async)
    uint32_t sb = sbase + SM_STG + (uint32_t)slot * STG_SLOT;
#pragma unroll
    for (int j = 0; j < 4; j++) {
      int u = tid + 256 * j;            // 1024 16B-units: r=u>>3, kq=u&7
      int r = u >> 3, kq = u & 7;
      long long g = r0 + r;
      const float* src;
      if (c < NRCH) src = resd + (g < NA ? g * RD + (long long)c * KC + kq * 4 : 0);
      else          src = gext + (g < NA ? g * EXTW + (long long)(c - NRCH) * KC + kq * 4 : 0);
      cpasync16(sb + sw128((uint32_t)r * 128 + (uint32_t)kq * 16), src, g < NA ? 16 : 0);
    }
    CP_COMMIT();
  };
  auto bstage = [&](int c, int slot) {       // B chunk -> ring (8KB, L2-hot)
    const uint4* src = (const uint4*)(g_Bfrag + c * 1024);
    uint32_t dst = sbase + SM_B + (uint32_t)slot * B_SLOT;
#pragma unroll
    for (int j = 0; j < 2; j++) {
      int u = tid + 256 * j;
      cpasync16(dst + (uint32_t)u * 16, src + u, 16);
    }
    CP_COMMIT();
  };

  // prologue: stage(0), stage(1), B(0)
  stageChunk(0, 0);
  stageChunk(1, 1);
  bstage(0, 0);
  CP_WAIT(2);        // stage(0) done
  __syncthreads();
  // pre-loop convert: stage slot0 -> A slot0 (fp16, no residual)
  {
    uint32_t sb = sbase + SM_STG;
    uint32_t aH = sbase + SM_A;
#pragma unroll
    for (int j = 0; j < 4; j++) {
      int u = tid + 256 * j;
      int r = u >> 3, kq = u & 7;
      float4 f;
      lds128f(f, sb + sw128((uint32_t)r * 128 + (uint32_t)kq * 16));
      uint32_t h0 = h2pack(f.x, f.y), h1 = h2pack(f.z, f.w);
      uint32_t ao = sw64((uint32_t)r * 64 + (uint32_t)kq * 8);
      asm volatile("st.shared.v2.u32 [%0], {%1, %2};" :: "r"(aH + ao), "r"(h0), "r"(h1) : "memory");
    }
  }

  // warp tile 64(M) x 32(N)
  const int wm = (wid >> 2) * 64;
  const int fnBase = (wid & 3) * 4;
  float acc[4][4][4];
#pragma unroll
  for (int a = 0; a < 4; a++)
#pragma unroll
    for (int b2 = 0; b2 < 4; b2++)
#pragma unroll
      for (int e = 0; e < 4; e++) acc[a][b2][e] = 0.f;

  for (int c = 0; c < NCHT; c++) {
    CP_WAIT(0);        // all copies from previous iteration complete (own)
    __syncthreads();   // everyone's copies visible; prev compute done (slots free)
    if (c + 2 < NCHT) stageChunk(c + 2, (c + 2) % 3);
    if (c + 1 < NCHT) bstage(c + 1, (c + 1) % 3);

    const int rbuf = c & 1;
    const bool doNext = (c + 1 < NCHT);
    const uint32_t aR = sbase + SM_A + (uint32_t)rbuf * A_SLOT;
    const uint32_t aW = sbase + SM_A + (uint32_t)(rbuf ^ 1) * A_SLOT;
    const uint32_t bS = sbase + SM_B + (uint32_t)(c % 3) * B_SLOT;
    const uint32_t stW = sbase + SM_STG + (uint32_t)((c + 1) % 3) * STG_SLOT;

#pragma unroll
    for (int t = 0; t < 2; t++) {
      // producer: 2 f32 units from stage ring (LDS; latency hidden by MMAs)
      int u0 = tid + 512 * t, u1 = u0 + 256;
      float4 pf0, pf1;
      if (doNext) {
        lds128f(pf0, stW + sw128((uint32_t)(u0 >> 3) * 128 + (uint32_t)(u0 & 7) * 16));
        lds128f(pf1, stW + sw128((uint32_t)(u1 >> 3) * 128 + (uint32_t)(u1 & 7) * 16));
      }
      // B fragments (fp16, uint2 per nf)
      uint2 bq[4];
#pragma unroll
      for (int nf = 0; nf < 4; nf++) {
        uint32_t ba = bS + (uint32_t)((((fnBase + nf) * 2 + t) << 5) + lane) * 8;
        asm volatile("ld.shared.v2.u32 {%0,%1}, [%2];"
                     : "=r"(bq[nf].x), "=r"(bq[nf].y) : "r"(ba));
      }
      uint32_t aofs[4];
#pragma unroll
      for (int mf = 0; mf < 4; mf++)
        aofs[mf] = sw64((uint32_t)(wm + mf * 16 + (lane & 15)) * 64 +
                        (uint32_t)t * 32 + (uint32_t)(lane >> 4) * 16);

      // single pass: 16 MMAs, all-distinct accumulators; A ldm4 pipelined 1 mf ahead
      {
        uint32_t a0[4], a1[4];
        ldm4(a0, aR + aofs[0]);
#pragma unroll
        for (int mf = 0; mf < 4; mf++) {
          if (mf < 3) ldm4(a1, aR + aofs[mf + 1]);
#pragma unroll
          for (int nf = 0; nf < 4; nf++)
            mma16816h(acc[mf][nf], a0, bq[nf].x, bq[nf].y);
          if (mf < 3) { a0[0] = a1[0]; a0[1] = a1[1]; a0[2] = a1[2]; a0[3] = a1[3]; }
        }
      }

      // producer: convert + store into next A buffer (fp16 only)
      if (doNext) {
        uint32_t h0 = h2pack(pf0.x, pf0.y), h1 = h2pack(pf0.z, pf0.w);
        uint32_t ao0 = sw64((uint32_t)(u0 >> 3) * 64 + (uint32_t)(u0 & 7) * 8);
        asm volatile("st.shared.v2.u32 [%0], {%1, %2};" :: "r"(aW + ao0), "r"(h0), "r"(h1) : "memory");
        uint32_t h2 = h2pack(pf1.x, pf1.y), h3 = h2pack(pf1.z, pf1.w);
        uint32_t ao1 = sw64((uint32_t)(u1 >> 3) * 64 + (uint32_t)(u1 & 7) * 8);
        asm volatile("st.shared.v2.u32 [%0], {%1, %2};" :: "r"(aW + ao1), "r"(h2), "r"(h3) : "memory");
      }
    }
  }

  // ---- epilogue: relu + float2 stores straight from fragments ----
  const int wn = (wid & 3) * 32;
#pragma unroll
  for (int mf = 0; mf < 4; mf++) {
    long long r = (long long)r0 + wm + mf * 16 + (lane >> 2);
#pragma unroll
    for (int nf = 0; nf < 4; nf++) {
      int cb = wn + nf * 8 + 2 * (lane & 3);
      if (r < NA) {
        float2 w;
        w.x = fmaxf(acc[mf][nf][0], 0.f);
        w.y = fmaxf(acc[mf][nf][1], 0.f);
        *(float2*)(outp + r * FD + cb) = w;
      }
      if (r + 8 < NA) {
        float2 w;
        w.x = fmaxf(acc[mf][nf][2], 0.f);
        w.y = fmaxf(acc[mf][nf][3], 0.f);
        *(float2*)(outp + (r + 8) * FD + cb) = w;
      }
    }
  }
}

extern "C" void kernel_launch(void* const* d_in, const int* in_sizes, int n_in,
                              void* d_out, int out_size) {
  const float* atoms0 = (const float*)d_in[0];
  const float* resd0  = (const float*)d_in[1];
  const int*   same0  = (const int*)d_in[2];
  const int*   diff0  = (const int*)d_in[3];
  const float* atoms1 = (const float*)d_in[4];
  const float* resd1  = (const float*)d_in[5];
  const int*   same1  = (const int*)d_in[6];
  const int*   diff1  = (const int*)d_in[7];
  const float* Wv  = (const float*)d_in[8];
  const float* Wr  = (const float*)d_in[9];
  const float* Wsr = (const float*)d_in[10];
  const float* Wdr = (const float*)d_in[11];
  float* out = (float*)d_out;

  cudaFuncSetAttribute(gnn_mma_kernel, cudaFuncAttributeMaxDynamicSharedMemorySize, SM_TOTAL);

  prep_kernel<<<BAKE_BLKS + IDX_BLKS + GATH_BLKS, 256>>>(
      Wr, Wv, Wsr, Wdr, atoms0, atoms1, same0, diff0, same1, diff1, out);
  gnn_mma_kernel<<<2 * CTAS, 256, SM_TOTAL>>>(resd0, resd1, out);
}